// round 14
// baseline (speedup 1.0000x reference)
#include <cuda_runtime.h>
#include <cuda_fp16.h>
#include <math.h>

#define D         128
#define NCOLS     256
#define MAX_NODES 100000
#define G_CTAS    782                    // ceil(100000 / 128)

typedef unsigned int u32;

// P (layer-1 pre-bias activations, A|B halves; b1 folded into A half), fp16
__device__ __half g_Ph[(size_t)MAX_NODES * NCOLS];
// W1 as paired fp16 B-fragments: ((jp*8 + kb)*32 + lane) -> uint4
//   {n-tile 2jp word0, word1, n-tile 2jp+1 word0, word1}
__device__ uint4 g_W4[16 * 8 * 32];

// ============================================================================
// helpers
// ============================================================================
__device__ __forceinline__ u32 f2h2(float lo, float hi) {
    u32 r;
    asm("cvt.rn.f16x2.f32 %0, %1, %2;" : "=r"(r) : "f"(hi), "f"(lo));
    return r;
}

__device__ __forceinline__ void mma_f16(float* d, const u32* a, u32 b0, u32 b1) {
    asm volatile(
        "mma.sync.aligned.m16n8k16.row.col.f32.f16.f16.f32 "
        "{%0, %1, %2, %3}, {%4, %5, %6, %7}, {%8, %9}, {%0, %1, %2, %3};"
        : "+f"(d[0]), "+f"(d[1]), "+f"(d[2]), "+f"(d[3])
        : "r"(a[0]), "r"(a[1]), "r"(a[2]), "r"(a[3]), "r"(b0), "r"(b1));
}

// ============================================================================
// Kernel 0: W1 -> paired fp16 B-fragments. grid=16 (jp), block=256 (kb,lane).
//   Bmat[n,k] = W1[n,k] (n<128) | W1[n-128, 128+k] (n>=128)
// ============================================================================
__global__ void prep_w_kernel(const float* __restrict__ W1)
{
    const int jp   = blockIdx.x;
    const int kb   = threadIdx.x >> 5;
    const int lane = threadIdx.x & 31;
    const int n0   = jp * 16 + (lane >> 2);
    const int n1   = n0 + 8;
    const int k0   = kb * 16 + (lane & 3) * 2;

    const float* r0 = (n0 < 128) ? (W1 + (size_t)n0 * NCOLS)
                                 : (W1 + (size_t)(n0 - 128) * NCOLS + 128);
    const float* r1 = (n1 < 128) ? (W1 + (size_t)n1 * NCOLS)
                                 : (W1 + (size_t)(n1 - 128) * NCOLS + 128);

    g_W4[(jp * 8 + kb) * 32 + lane] =
        make_uint4(f2h2(r0[k0], r0[k0 + 1]), f2h2(r0[k0 + 8], r0[k0 + 9]),
                   f2h2(r1[k0], r1[k0 + 1]), f2h2(r1[k0 + 8], r1[k0 + 9]));
}

// ============================================================================
// Kernel 1: P = x @ Bmat^T (fp16 m16n8k16, fp32 accum), x converted to fp16
// fragments in registers (no smem, no sync, 2x in-CTA read redundancy).
// grid = G_CTAS (128 rows each), block = 512 (16 warps: 8 M x 2 N,
// warp tile 16 x 128). b1 folded into cols < 128. P stored fp16.
// ============================================================================
__global__ __launch_bounds__(512, 1) void precompute_kernel(
    const float* __restrict__ x,
    const float* __restrict__ b1,
    int nN)
{
    const int tid  = threadIdx.x;
    const int wid  = tid >> 5;
    const int lane = tid & 31;
    const int wmg  = wid & 7;             // M-warp (8)
    const int wng  = wid >> 3;            // N-warp (2)
    const int r    = lane >> 2;
    const int c2   = (lane & 3) * 2;
    const int m0   = blockIdx.x * 128;
    const int mA   = m0 + wmg * 16 + r;   // this thread's upper row
    const int mB   = mA + 8;              // lower row

    float acc[16][4];
    #pragma unroll
    for (int j = 0; j < 16; j++)
        #pragma unroll
        for (int q = 0; q < 4; q++) acc[j][q] = 0.f;

    const float2 z = make_float2(0.f, 0.f);
    const float* pA = x + (size_t)mA * D;
    const float* pB = x + (size_t)mB * D;
    const bool okA = (mA < nN);
    const bool okB = (mB < nN);

    #pragma unroll
    for (int kb = 0; kb < 8; kb++) {
        const int k = kb * 16 + c2;

        // A fragment: 4 fp32-pair loads + 4 cvt
        float2 v0 = okA ? *reinterpret_cast<const float2*>(pA + k)     : z;
        float2 v1 = okB ? *reinterpret_cast<const float2*>(pB + k)     : z;
        float2 v2 = okA ? *reinterpret_cast<const float2*>(pA + k + 8) : z;
        float2 v3 = okB ? *reinterpret_cast<const float2*>(pB + k + 8) : z;
        u32 a[4];
        a[0] = f2h2(v0.x, v0.y);
        a[1] = f2h2(v1.x, v1.y);
        a[2] = f2h2(v2.x, v2.y);
        a[3] = f2h2(v3.x, v3.y);

        // B fragments: 8 pair-tiles (16 n-tiles), 32 HMMA
        #pragma unroll
        for (int jp = 0; jp < 8; jp++) {
            uint4 B = g_W4[((wng * 8 + jp) * 8 + kb) * 32 + lane];
            mma_f16(acc[2 * jp],     a, B.x, B.y);
            mma_f16(acc[2 * jp + 1], a, B.z, B.w);
        }
    }

    // ---- epilogue: + b1 (cols<128 only), fp16 store ----
    #pragma unroll
    for (int j = 0; j < 16; j++) {
        const int col = (wng * 16 + j) * 8 + c2;
        float2 bias = make_float2(0.f, 0.f);
        if (col < 128)
            bias = *reinterpret_cast<const float2*>(b1 + col);
        if (okA) {
            *reinterpret_cast<u32*>(&g_Ph[(size_t)mA * NCOLS + col]) =
                f2h2(acc[j][0] + bias.x, acc[j][1] + bias.y);
        }
        if (okB) {
            *reinterpret_cast<u32*>(&g_Ph[(size_t)mB * NCOLS + col]) =
                f2h2(acc[j][2] + bias.x, acc[j][3] + bias.y);
        }
    }
}

// ============================================================================
// Kernel 2: per-edge MLP tail. 8 lanes per edge, 4 edge-slots per warp,
// ILP=3 (12 edges per warp iteration). launch_bounds forces 3 CTAs/SM.
//   v = sum_j max(PA[src][j] + PB[dst][j], 0) * w2[j]    (b1 already in PA)
//   out[e] = sigmoid(relu(v + b2))
// ============================================================================
__device__ __forceinline__ float dot16(uint4 ua, uint4 uc, const float* w) {
    const __half2 z2 = __float2half2_rn(0.f);
    const __half2* a2 = reinterpret_cast<const __half2*>(&ua);
    const __half2* c2 = reinterpret_cast<const __half2*>(&uc);
    float v = 0.f;
    #pragma unroll
    for (int i = 0; i < 4; i++) {
        __half2 h = __hmax2(__hadd2(a2[i], c2[i]), z2);
        float2 f = __half22float2(h);
        v = fmaf(f.x, w[2 * i], v);
        v = fmaf(f.y, w[2 * i + 1], v);
    }
    return v;
}

__global__ __launch_bounds__(256, 3) void edge_kernel(
    const void* __restrict__ edge_index,
    const float* __restrict__ W2,
    const float* __restrict__ b2,
    float* __restrict__ out,
    int E)
{
    const int lane   = threadIdx.x & 31;
    const int slot   = lane >> 3;
    const int sub    = lane & 7;
    const int warp   = (blockIdx.x * blockDim.x + threadIdx.x) >> 5;
    const int nwarps = (gridDim.x * blockDim.x) >> 5;

    // dtype sniff: LE int64 (<2^31) => all odd 32-bit words zero
    const int* ei32 = (const int*)edge_index;
    int det = 0;
    #pragma unroll
    for (int i = 1; i < 16; i += 2) det |= __ldg(&ei32[i]);
    const bool is64 = (det == 0);
    const long long* ei64 = (const long long*)edge_index;

    float w0[8], w1[8];
    {
        const float4* w4 = reinterpret_cast<const float4*>(W2);
        float4 p0 = w4[sub * 2], p1 = w4[sub * 2 + 1];
        float4 p2 = w4[16 + sub * 2], p3 = w4[16 + sub * 2 + 1];
        w0[0]=p0.x; w0[1]=p0.y; w0[2]=p0.z; w0[3]=p0.w;
        w0[4]=p1.x; w0[5]=p1.y; w0[6]=p1.z; w0[7]=p1.w;
        w1[0]=p2.x; w1[1]=p2.y; w1[2]=p2.z; w1[3]=p2.w;
        w1[4]=p3.x; w1[5]=p3.y; w1[6]=p3.z; w1[7]=p3.w;
    }
    const float b2v = *b2;
    const __half* Ph = g_Ph;

    for (int eb = warp * 12; eb < E; eb += nwarps * 12) {
        int er[3], s[3], t[3];
        #pragma unroll
        for (int q = 0; q < 3; q++) {
            er[q] = eb + q * 4 + slot;
            int e = (er[q] < E) ? er[q] : (E - 1);
            if (is64) { s[q] = (int)ei64[e]; t[q] = (int)ei64[E + e]; }
            else      { s[q] = ei32[e];      t[q] = ei32[E + e]; }
        }

        uint4 a0[3], a1[3], c0[3], c1[3];
        #pragma unroll
        for (int q = 0; q < 3; q++) {
            const __half* rA = Ph + (size_t)s[q] * NCOLS;
            const __half* rC = Ph + (size_t)t[q] * NCOLS + 128;
            a0[q] = *reinterpret_cast<const uint4*>(rA + sub * 8);
            a1[q] = *reinterpret_cast<const uint4*>(rA + 64 + sub * 8);
            c0[q] = *reinterpret_cast<const uint4*>(rC + sub * 8);
            c1[q] = *reinterpret_cast<const uint4*>(rC + 64 + sub * 8);
        }

        float v[3];
        #pragma unroll
        for (int q = 0; q < 3; q++)
            v[q] = dot16(a0[q], c0[q], w0) + dot16(a1[q], c1[q], w1);

        #pragma unroll
        for (int o = 4; o > 0; o >>= 1) {
            #pragma unroll
            for (int q = 0; q < 3; q++)
                v[q] += __shfl_xor_sync(0xFFFFFFFFu, v[q], o);
        }

        if (sub == 0) {
            #pragma unroll
            for (int q = 0; q < 3; q++) {
                if (er[q] < E) {
                    float h = fmaxf(v[q] + b2v, 0.f);
                    out[er[q]] = 1.0f / (1.0f + __expf(-h));
                }
            }
        }
    }
}

// ============================================================================
// Launch
// Inputs: x[f32 N*128], edge_index[2*E i32/i64], W1[f32 128*256], b1[f32 128],
//         W2[f32 128], b2[f32 1]. Output: f32 E.
// ============================================================================
extern "C" void kernel_launch(void* const* d_in, const int* in_sizes, int n_in,
                              void* d_out, int out_size)
{
    const float* x  = (const float*)d_in[0];
    const void*  ei = d_in[1];
    const float* W1 = (const float*)d_in[2];
    const float* b1 = (const float*)d_in[3];
    const float* W2 = (const float*)d_in[4];
    const float* b2 = (const float*)d_in[5];
    float*       out = (float*)d_out;

    const int N = in_sizes[0] / D;   // 100000
    const int E = in_sizes[1] / 2;   // 625000

    prep_w_kernel<<<16, 256>>>(W1);
    precompute_kernel<<<G_CTAS, 512>>>(x, b1, N);
    edge_kernel<<<1332, 256>>>(ei, W2, b2, out, E);
}

// round 15
// speedup vs baseline: 1.0384x; 1.0384x over previous
#include <cuda_runtime.h>
#include <cuda_fp16.h>
#include <math.h>

#define D         128
#define NCOLS     256
#define MAX_NODES 100000
#define N_CTAS    1563                   // ceil(100000 / 64)
#define MAX_MT    (N_CTAS * 4)           // 6252 m-tiles of 16 rows (padded)

typedef unsigned int u32;

// P (layer-1 pre-bias activations, A|B halves; b1 folded into A half), fp16
__device__ __half g_Ph[(size_t)MAX_NODES * NCOLS];
// W1 as paired fp16 B-fragments: ((jp*8 + kb)*32 + lane) -> uint4
__device__ uint4 g_W4[16 * 8 * 32];
// x as fp16 A-fragments: ((mt*8 + kb)*32 + lane) -> uint4 {a0,a1,a2,a3}
__device__ uint4 g_X4[(size_t)MAX_MT * 8 * 32];

// ============================================================================
// helpers
// ============================================================================
__device__ __forceinline__ u32 f2h2(float lo, float hi) {
    u32 r;
    asm("cvt.rn.f16x2.f32 %0, %1, %2;" : "=r"(r) : "f"(hi), "f"(lo));
    return r;
}

__device__ __forceinline__ void mma_f16(float* d, const u32* a, u32 b0, u32 b1) {
    asm volatile(
        "mma.sync.aligned.m16n8k16.row.col.f32.f16.f16.f32 "
        "{%0, %1, %2, %3}, {%4, %5, %6, %7}, {%8, %9}, {%0, %1, %2, %3};"
        : "+f"(d[0]), "+f"(d[1]), "+f"(d[2]), "+f"(d[3])
        : "r"(a[0]), "r"(a[1]), "r"(a[2]), "r"(a[3]), "r"(b0), "r"(b1));
}

// ============================================================================
// Kernel 0 (merged): x -> fp16 A-fragments; blocks 0..15 also convert W1 ->
// paired fp16 B-fragments. grid = MAX_MT, block = 256 (kb x lane).
// ============================================================================
__global__ void prep_kernel(const float* __restrict__ x,
                            const float* __restrict__ W1,
                            int nN)
{
    const int mt   = blockIdx.x;
    const int kb   = threadIdx.x >> 5;
    const int lane = threadIdx.x & 31;
    const int r    = lane >> 2;
    const int k    = kb * 16 + (lane & 3) * 2;

    // ---- W part (first 16 blocks only) ----
    if (mt < 16) {
        const int n0 = mt * 16 + (lane >> 2);
        const int n1 = n0 + 8;
        const int k0 = kb * 16 + (lane & 3) * 2;
        const float* r0 = (n0 < 128) ? (W1 + (size_t)n0 * NCOLS)
                                     : (W1 + (size_t)(n0 - 128) * NCOLS + 128);
        const float* r1 = (n1 < 128) ? (W1 + (size_t)n1 * NCOLS)
                                     : (W1 + (size_t)(n1 - 128) * NCOLS + 128);
        g_W4[(mt * 8 + kb) * 32 + lane] =
            make_uint4(f2h2(r0[k0], r0[k0 + 1]), f2h2(r0[k0 + 8], r0[k0 + 9]),
                       f2h2(r1[k0], r1[k0 + 1]), f2h2(r1[k0 + 8], r1[k0 + 9]));
    }

    // ---- X part (all blocks) ----
    const int m = mt * 16 + r;
    const float2 z = make_float2(0.f, 0.f);
    const float* p0 = x + (size_t)m * D + k;
    const float* p1 = x + (size_t)(m + 8) * D + k;
    float2 v0 = (m < nN)     ? *reinterpret_cast<const float2*>(p0)     : z;
    float2 v2 = (m < nN)     ? *reinterpret_cast<const float2*>(p0 + 8) : z;
    float2 v1 = (m + 8 < nN) ? *reinterpret_cast<const float2*>(p1)     : z;
    float2 v3 = (m + 8 < nN) ? *reinterpret_cast<const float2*>(p1 + 8) : z;

    g_X4[((size_t)mt * 8 + kb) * 32 + lane] =
        make_uint4(f2h2(v0.x, v0.y), f2h2(v1.x, v1.y),
                   f2h2(v2.x, v2.y), f2h2(v3.x, v3.y));
}

// ============================================================================
// Kernel 1: P = x @ Bmat^T (fp16 m16n8k16, fp32 accum), pure fragment loads.
// grid = (N_CTAS, 2): x = 64-row block, y = 128-col half. block = 256
// (8 warps: 2 M x 4 N, warp tile 32x32). 32 accum regs -> 3 CTAs/SM.
// b1 folded into cols < 128. P stored fp16.
// ============================================================================
__global__ __launch_bounds__(256, 3) void precompute_kernel(
    const float* __restrict__ b1, int nN)
{
    const int tid  = threadIdx.x;
    const int wid  = tid >> 5;
    const int lane = tid & 31;
    const int wmg  = wid & 1;             // M-warp (2)
    const int wng  = wid >> 1;            // N-warp (4)
    const int half = blockIdx.y;          // col half (0/1)
    const int wjt  = half * 16 + wng * 4; // first n-tile of this warp
    const int r    = lane >> 2;
    const int c2   = (lane & 3) * 2;
    const int m0   = blockIdx.x * 64;
    const int mtb  = blockIdx.x * 4 + wmg * 2;

    float acc[2][4][4];
    #pragma unroll
    for (int i = 0; i < 2; i++)
        #pragma unroll
        for (int j = 0; j < 4; j++)
            #pragma unroll
            for (int q = 0; q < 4; q++) acc[i][j][q] = 0.f;

    #pragma unroll
    for (int kb = 0; kb < 8; kb++) {
        u32 a[2][4];
        #pragma unroll
        for (int i = 0; i < 2; i++) {
            uint4 A = g_X4[((size_t)(mtb + i) * 8 + kb) * 32 + lane];
            a[i][0] = A.x; a[i][1] = A.y; a[i][2] = A.z; a[i][3] = A.w;
        }
        #pragma unroll
        for (int jp2 = 0; jp2 < 2; jp2++) {
            const int jp = half * 8 + wng * 2 + jp2;
            uint4 B = g_W4[(jp * 8 + kb) * 32 + lane];
            mma_f16(acc[0][2 * jp2],     a[0], B.x, B.y);
            mma_f16(acc[1][2 * jp2],     a[1], B.x, B.y);
            mma_f16(acc[0][2 * jp2 + 1], a[0], B.z, B.w);
            mma_f16(acc[1][2 * jp2 + 1], a[1], B.z, B.w);
        }
    }

    // ---- epilogue: + b1 (cols<128 only), fp16 store ----
    #pragma unroll
    for (int j = 0; j < 4; j++) {
        const int col = (wjt + j) * 8 + c2;
        float2 bias = make_float2(0.f, 0.f);
        if (col < 128)
            bias = *reinterpret_cast<const float2*>(b1 + col);
        #pragma unroll
        for (int i = 0; i < 2; i++) {
            const int mA = m0 + wmg * 32 + i * 16 + r;
            if (mA < nN) {
                *reinterpret_cast<u32*>(&g_Ph[(size_t)mA * NCOLS + col]) =
                    f2h2(acc[i][j][0] + bias.x, acc[i][j][1] + bias.y);
            }
            const int mB = mA + 8;
            if (mB < nN) {
                *reinterpret_cast<u32*>(&g_Ph[(size_t)mB * NCOLS + col]) =
                    f2h2(acc[i][j][2] + bias.x, acc[i][j][3] + bias.y);
            }
        }
    }
}

// ============================================================================
// Kernel 2: per-edge MLP tail (R13 verbatim). 8 lanes per edge, 4 edge-slots
// per warp, ILP=3 (12 edges per warp iteration).
//   v = sum_j max(PA[src][j] + PB[dst][j], 0) * w2[j]    (b1 already in PA)
//   out[e] = sigmoid(relu(v + b2))
// ============================================================================
__device__ __forceinline__ float dot16(uint4 ua, uint4 uc, const float* w) {
    const __half2 z2 = __float2half2_rn(0.f);
    const __half2* a2 = reinterpret_cast<const __half2*>(&ua);
    const __half2* c2 = reinterpret_cast<const __half2*>(&uc);
    float v = 0.f;
    #pragma unroll
    for (int i = 0; i < 4; i++) {
        __half2 h = __hmax2(__hadd2(a2[i], c2[i]), z2);
        float2 f = __half22float2(h);
        v = fmaf(f.x, w[2 * i], v);
        v = fmaf(f.y, w[2 * i + 1], v);
    }
    return v;
}

__global__ __launch_bounds__(256) void edge_kernel(
    const void* __restrict__ edge_index,
    const float* __restrict__ W2,
    const float* __restrict__ b2,
    float* __restrict__ out,
    int E)
{
    const int lane   = threadIdx.x & 31;
    const int slot   = lane >> 3;
    const int sub    = lane & 7;
    const int warp   = (blockIdx.x * blockDim.x + threadIdx.x) >> 5;
    const int nwarps = (gridDim.x * blockDim.x) >> 5;

    // dtype sniff: LE int64 (<2^31) => all odd 32-bit words zero
    const int* ei32 = (const int*)edge_index;
    int det = 0;
    #pragma unroll
    for (int i = 1; i < 16; i += 2) det |= __ldg(&ei32[i]);
    const bool is64 = (det == 0);
    const long long* ei64 = (const long long*)edge_index;

    float w0[8], w1[8];
    {
        const float4* w4 = reinterpret_cast<const float4*>(W2);
        float4 p0 = w4[sub * 2], p1 = w4[sub * 2 + 1];
        float4 p2 = w4[16 + sub * 2], p3 = w4[16 + sub * 2 + 1];
        w0[0]=p0.x; w0[1]=p0.y; w0[2]=p0.z; w0[3]=p0.w;
        w0[4]=p1.x; w0[5]=p1.y; w0[6]=p1.z; w0[7]=p1.w;
        w1[0]=p2.x; w1[1]=p2.y; w1[2]=p2.z; w1[3]=p2.w;
        w1[4]=p3.x; w1[5]=p3.y; w1[6]=p3.z; w1[7]=p3.w;
    }
    const float b2v = *b2;
    const __half* Ph = g_Ph;

    for (int eb = warp * 12; eb < E; eb += nwarps * 12) {
        int er[3], s[3], t[3];
        #pragma unroll
        for (int q = 0; q < 3; q++) {
            er[q] = eb + q * 4 + slot;
            int e = (er[q] < E) ? er[q] : (E - 1);
            if (is64) { s[q] = (int)ei64[e]; t[q] = (int)ei64[E + e]; }
            else      { s[q] = ei32[e];      t[q] = ei32[E + e]; }
        }

        uint4 a0[3], a1[3], c0[3], c1[3];
        #pragma unroll
        for (int q = 0; q < 3; q++) {
            const __half* rA = Ph + (size_t)s[q] * NCOLS;
            const __half* rC = Ph + (size_t)t[q] * NCOLS + 128;
            a0[q] = *reinterpret_cast<const uint4*>(rA + sub * 8);
            a1[q] = *reinterpret_cast<const uint4*>(rA + 64 + sub * 8);
            c0[q] = *reinterpret_cast<const uint4*>(rC + sub * 8);
            c1[q] = *reinterpret_cast<const uint4*>(rC + 64 + sub * 8);
        }

        float v[3];
        #pragma unroll
        for (int q = 0; q < 3; q++)
            v[q] = dot16(a0[q], c0[q], w0) + dot16(a1[q], c1[q], w1);

        #pragma unroll
        for (int o = 4; o > 0; o >>= 1) {
            #pragma unroll
            for (int q = 0; q < 3; q++)
                v[q] += __shfl_xor_sync(0xFFFFFFFFu, v[q], o);
        }

        if (sub == 0) {
            #pragma unroll
            for (int q = 0; q < 3; q++) {
                if (er[q] < E) {
                    float h = fmaxf(v[q] + b2v, 0.f);
                    out[er[q]] = 1.0f / (1.0f + __expf(-h));
                }
            }
        }
    }
}

// ============================================================================
// Launch
// Inputs: x[f32 N*128], edge_index[2*E i32/i64], W1[f32 128*256], b1[f32 128],
//         W2[f32 128], b2[f32 1]. Output: f32 E.
// ============================================================================
extern "C" void kernel_launch(void* const* d_in, const int* in_sizes, int n_in,
                              void* d_out, int out_size)
{
    const float* x  = (const float*)d_in[0];
    const void*  ei = d_in[1];
    const float* W1 = (const float*)d_in[2];
    const float* b1 = (const float*)d_in[3];
    const float* W2 = (const float*)d_in[4];
    const float* b2 = (const float*)d_in[5];
    float*       out = (float*)d_out;

    const int N = in_sizes[0] / D;   // 100000
    const int E = in_sizes[1] / 2;   // 625000

    prep_kernel<<<MAX_MT, 256>>>(x, W1, N);
    precompute_kernel<<<dim3(N_CTAS, 2), 256>>>(b1, N);
    edge_kernel<<<1184, 256>>>(ei, W2, b2, out, E);
}

// round 16
// speedup vs baseline: 1.0753x; 1.0355x over previous
#include <cuda_runtime.h>
#include <cuda_fp16.h>
#include <math.h>

#define D         128
#define NCOLS     256
#define MAX_NODES 100000
#define N_CTAS    1563                   // ceil(100000 / 64)
#define MAX_MT    (N_CTAS * 4)           // 6252 m-tiles of 16 rows (padded)

typedef unsigned int u32;

// P (layer-1 pre-bias activations, A|B halves; b1 folded into A half), fp16
__device__ __half g_Ph[(size_t)MAX_NODES * NCOLS];
// W1 as paired fp16 B-fragments: ((jp*8 + kb)*32 + lane) -> uint4
__device__ uint4 g_W4[16 * 8 * 32];
// x as fp16 A-fragments: ((mt*8 + kb)*32 + lane) -> uint4 {a0,a1,a2,a3}
__device__ uint4 g_X4[(size_t)MAX_MT * 8 * 32];

// ============================================================================
// helpers
// ============================================================================
__device__ __forceinline__ u32 f2h2(float lo, float hi) {
    u32 r;
    asm("cvt.rn.f16x2.f32 %0, %1, %2;" : "=r"(r) : "f"(hi), "f"(lo));
    return r;
}

__device__ __forceinline__ void mma_f16(float* d, const u32* a, u32 b0, u32 b1) {
    asm volatile(
        "mma.sync.aligned.m16n8k16.row.col.f32.f16.f16.f32 "
        "{%0, %1, %2, %3}, {%4, %5, %6, %7}, {%8, %9}, {%0, %1, %2, %3};"
        : "+f"(d[0]), "+f"(d[1]), "+f"(d[2]), "+f"(d[3])
        : "r"(a[0]), "r"(a[1]), "r"(a[2]), "r"(a[3]), "r"(b0), "r"(b1));
}

// ============================================================================
// Kernel 0 (merged): x -> fp16 A-fragments; blocks 0..15 also convert W1 ->
// paired fp16 B-fragments. grid = MAX_MT, block = 256 (kb x lane).
// ============================================================================
__global__ void prep_kernel(const float* __restrict__ x,
                            const float* __restrict__ W1,
                            int nN)
{
    const int mt   = blockIdx.x;
    const int kb   = threadIdx.x >> 5;
    const int lane = threadIdx.x & 31;
    const int r    = lane >> 2;
    const int k    = kb * 16 + (lane & 3) * 2;

    if (mt < 16) {
        const int n0 = mt * 16 + (lane >> 2);
        const int n1 = n0 + 8;
        const int k0 = kb * 16 + (lane & 3) * 2;
        const float* r0 = (n0 < 128) ? (W1 + (size_t)n0 * NCOLS)
                                     : (W1 + (size_t)(n0 - 128) * NCOLS + 128);
        const float* r1 = (n1 < 128) ? (W1 + (size_t)n1 * NCOLS)
                                     : (W1 + (size_t)(n1 - 128) * NCOLS + 128);
        g_W4[(mt * 8 + kb) * 32 + lane] =
            make_uint4(f2h2(r0[k0], r0[k0 + 1]), f2h2(r0[k0 + 8], r0[k0 + 9]),
                       f2h2(r1[k0], r1[k0 + 1]), f2h2(r1[k0 + 8], r1[k0 + 9]));
    }

    const int m = mt * 16 + r;
    const float2 z = make_float2(0.f, 0.f);
    const float* p0 = x + (size_t)m * D + k;
    const float* p1 = x + (size_t)(m + 8) * D + k;
    float2 v0 = (m < nN)     ? *reinterpret_cast<const float2*>(p0)     : z;
    float2 v2 = (m < nN)     ? *reinterpret_cast<const float2*>(p0 + 8) : z;
    float2 v1 = (m + 8 < nN) ? *reinterpret_cast<const float2*>(p1)     : z;
    float2 v3 = (m + 8 < nN) ? *reinterpret_cast<const float2*>(p1 + 8) : z;

    g_X4[((size_t)mt * 8 + kb) * 32 + lane] =
        make_uint4(f2h2(v0.x, v0.y), f2h2(v1.x, v1.y),
                   f2h2(v2.x, v2.y), f2h2(v3.x, v3.y));
}

// ============================================================================
// Kernel 1: P = x @ Bmat^T (fp16 m16n8k16, fp32 accum), pure fragment loads.
// (R13 verbatim) grid = N_CTAS (64 rows), block = 256 (2 M x 4 N warps,
// warp tile 32x64). b1 folded into cols < 128. P stored fp16.
// ============================================================================
__global__ __launch_bounds__(256, 2) void precompute_kernel(
    const float* __restrict__ b1, int nN)
{
    const int tid  = threadIdx.x;
    const int wid  = tid >> 5;
    const int lane = tid & 31;
    const int wmg  = wid & 1;
    const int wng  = wid >> 1;
    const int wm   = wmg * 32;
    const int wjt  = wng * 8;
    const int r    = lane >> 2;
    const int c2   = (lane & 3) * 2;
    const int m0   = blockIdx.x * 64;
    const int mtb  = blockIdx.x * 4 + wmg * 2;

    float acc[2][8][4];
    #pragma unroll
    for (int i = 0; i < 2; i++)
        #pragma unroll
        for (int j = 0; j < 8; j++)
            #pragma unroll
            for (int q = 0; q < 4; q++) acc[i][j][q] = 0.f;

    #pragma unroll
    for (int kb = 0; kb < 8; kb++) {
        u32 a[2][4];
        #pragma unroll
        for (int i = 0; i < 2; i++) {
            uint4 A = g_X4[((size_t)(mtb + i) * 8 + kb) * 32 + lane];
            a[i][0] = A.x; a[i][1] = A.y; a[i][2] = A.z; a[i][3] = A.w;
        }
        #pragma unroll
        for (int jp = 0; jp < 4; jp++) {
            uint4 B = g_W4[(((wjt >> 1) + jp) * 8 + kb) * 32 + lane];
            mma_f16(acc[0][2 * jp],     a[0], B.x, B.y);
            mma_f16(acc[1][2 * jp],     a[1], B.x, B.y);
            mma_f16(acc[0][2 * jp + 1], a[0], B.z, B.w);
            mma_f16(acc[1][2 * jp + 1], a[1], B.z, B.w);
        }
    }

    #pragma unroll
    for (int j = 0; j < 8; j++) {
        const int col = (wjt + j) * 8 + c2;
        float2 bias = make_float2(0.f, 0.f);
        if (col < 128)
            bias = *reinterpret_cast<const float2*>(b1 + col);
        #pragma unroll
        for (int i = 0; i < 2; i++) {
            const int mA = m0 + wm + i * 16 + r;
            if (mA < nN) {
                *reinterpret_cast<u32*>(&g_Ph[(size_t)mA * NCOLS + col]) =
                    f2h2(acc[i][j][0] + bias.x, acc[i][j][1] + bias.y);
            }
            const int mB = mA + 8;
            if (mB < nN) {
                *reinterpret_cast<u32*>(&g_Ph[(size_t)mB * NCOLS + col]) =
                    f2h2(acc[i][j][2] + bias.x, acc[i][j][3] + bias.y);
            }
        }
    }
}

// ============================================================================
// Kernel 2: per-edge MLP tail. 8 lanes/edge, 4 slots/warp, ILP=3 (12 edges
// per iteration) + software-pipelined index prefetch (next iteration's
// indices load during current iteration's compute).
//   v = sum_j max(PA[src][j] + PB[dst][j], 0) * w2[j]    (b1 already in PA)
//   out[e] = sigmoid(relu(v + b2))
// ============================================================================
__device__ __forceinline__ float dot16(uint4 ua, uint4 uc, const float* w) {
    const __half2 z2 = __float2half2_rn(0.f);
    const __half2* a2 = reinterpret_cast<const __half2*>(&ua);
    const __half2* c2 = reinterpret_cast<const __half2*>(&uc);
    float v = 0.f;
    #pragma unroll
    for (int i = 0; i < 4; i++) {
        __half2 h = __hmax2(__hadd2(a2[i], c2[i]), z2);
        float2 f = __half22float2(h);
        v = fmaf(f.x, w[2 * i], v);
        v = fmaf(f.y, w[2 * i + 1], v);
    }
    return v;
}

__global__ __launch_bounds__(256, 3) void edge_kernel(
    const void* __restrict__ edge_index,
    const float* __restrict__ W2,
    const float* __restrict__ b2,
    float* __restrict__ out,
    int E)
{
    const int lane   = threadIdx.x & 31;
    const int slot   = lane >> 3;
    const int sub    = lane & 7;
    const int warp   = (blockIdx.x * blockDim.x + threadIdx.x) >> 5;
    const int nwarps = (gridDim.x * blockDim.x) >> 5;
    const int step   = nwarps * 12;

    // dtype sniff: LE int64 (<2^31) => all odd 32-bit words zero
    const int* ei32 = (const int*)edge_index;
    int det = 0;
    #pragma unroll
    for (int i = 1; i < 16; i += 2) det |= __ldg(&ei32[i]);
    const bool is64 = (det == 0);
    const long long* ei64 = (const long long*)edge_index;

    float w0[8], w1[8];
    {
        const float4* w4 = reinterpret_cast<const float4*>(W2);
        float4 p0 = w4[sub * 2], p1 = w4[sub * 2 + 1];
        float4 p2 = w4[16 + sub * 2], p3 = w4[16 + sub * 2 + 1];
        w0[0]=p0.x; w0[1]=p0.y; w0[2]=p0.z; w0[3]=p0.w;
        w0[4]=p1.x; w0[5]=p1.y; w0[6]=p1.z; w0[7]=p1.w;
        w1[0]=p2.x; w1[1]=p2.y; w1[2]=p2.z; w1[3]=p2.w;
        w1[4]=p3.x; w1[5]=p3.y; w1[6]=p3.z; w1[7]=p3.w;
    }
    const float b2v = *b2;
    const __half* Ph = g_Ph;

    const int eb0 = warp * 12;
    if (eb0 >= E) return;

    // prologue: load indices for first iteration
    int s[3], t[3];
    #pragma unroll
    for (int q = 0; q < 3; q++) {
        int er = eb0 + q * 4 + slot;
        int e  = (er < E) ? er : (E - 1);
        if (is64) { s[q] = (int)ei64[e]; t[q] = (int)ei64[E + e]; }
        else      { s[q] = ei32[e];      t[q] = ei32[E + e]; }
    }

    for (int eb = eb0; eb < E; eb += step) {
        // gathers for current iteration (indices already resident)
        uint4 a0[3], a1[3], c0[3], c1[3];
        #pragma unroll
        for (int q = 0; q < 3; q++) {
            const __half* rA = Ph + (size_t)s[q] * NCOLS;
            const __half* rC = Ph + (size_t)t[q] * NCOLS + 128;
            a0[q] = *reinterpret_cast<const uint4*>(rA + sub * 8);
            a1[q] = *reinterpret_cast<const uint4*>(rA + 64 + sub * 8);
            c0[q] = *reinterpret_cast<const uint4*>(rC + sub * 8);
            c1[q] = *reinterpret_cast<const uint4*>(rC + 64 + sub * 8);
        }

        // prefetch indices for next iteration (overlaps with gathers/compute)
        const int nb = eb + step;
        if (nb < E) {
            #pragma unroll
            for (int q = 0; q < 3; q++) {
                int er = nb + q * 4 + slot;
                int e  = (er < E) ? er : (E - 1);
                if (is64) { s[q] = (int)ei64[e]; t[q] = (int)ei64[E + e]; }
                else      { s[q] = ei32[e];      t[q] = ei32[E + e]; }
            }
        }

        float v[3];
        #pragma unroll
        for (int q = 0; q < 3; q++)
            v[q] = dot16(a0[q], c0[q], w0) + dot16(a1[q], c1[q], w1);

        #pragma unroll
        for (int o = 4; o > 0; o >>= 1) {
            #pragma unroll
            for (int q = 0; q < 3; q++)
                v[q] += __shfl_xor_sync(0xFFFFFFFFu, v[q], o);
        }

        if (sub == 0) {
            #pragma unroll
            for (int q = 0; q < 3; q++) {
                int er = eb + q * 4 + slot;
                if (er < E) {
                    float h = fmaxf(v[q] + b2v, 0.f);
                    out[er] = 1.0f / (1.0f + __expf(-h));
                }
            }
        }
    }
}

// ============================================================================
// Launch
// Inputs: x[f32 N*128], edge_index[2*E i32/i64], W1[f32 128*256], b1[f32 128],
//         W2[f32 128], b2[f32 1]. Output: f32 E.
// ============================================================================
extern "C" void kernel_launch(void* const* d_in, const int* in_sizes, int n_in,
                              void* d_out, int out_size)
{
    const float* x  = (const float*)d_in[0];
    const void*  ei = d_in[1];
    const float* W1 = (const float*)d_in[2];
    const float* b1 = (const float*)d_in[3];
    const float* W2 = (const float*)d_in[4];
    const float* b2 = (const float*)d_in[5];
    float*       out = (float*)d_out;

    const int N = in_sizes[0] / D;   // 100000
    const int E = in_sizes[1] / 2;   // 625000

    prep_kernel<<<MAX_MT, 256>>>(x, W1, N);
    precompute_kernel<<<N_CTAS, 256>>>(b1, N);
    edge_kernel<<<1184, 256>>>(ei, W2, b2, out, E);
}

// round 17
// speedup vs baseline: 1.0832x; 1.0073x over previous
#include <cuda_runtime.h>
#include <cuda_fp16.h>
#include <math.h>

#define D         128
#define NCOLS     256
#define MAX_NODES 100000
#define N_CTAS    1563                   // ceil(100000 / 64)
#define MAX_MT    (N_CTAS * 4)           // 6252 m-tiles of 16 rows (padded)
#define PREP_CTAS ((MAX_MT + 1) / 2)     // 3126 (2 m-tiles per block)

typedef unsigned int u32;

// P (layer-1 pre-bias activations, A|B halves; b1 folded into A half), fp16
__device__ __half g_Ph[(size_t)MAX_NODES * NCOLS];
// W1 as paired fp16 B-fragments: ((jp*8 + kb)*32 + lane) -> uint4
__device__ uint4 g_W4[16 * 8 * 32];
// x as fp16 A-fragments: ((mt*8 + kb)*32 + lane) -> uint4 {a0,a1,a2,a3}
__device__ uint4 g_X4[(size_t)MAX_MT * 8 * 32];

// ============================================================================
// helpers
// ============================================================================
__device__ __forceinline__ u32 f2h2(float lo, float hi) {
    u32 r;
    asm("cvt.rn.f16x2.f32 %0, %1, %2;" : "=r"(r) : "f"(hi), "f"(lo));
    return r;
}

__device__ __forceinline__ void mma_f16(float* d, const u32* a, u32 b0, u32 b1) {
    asm volatile(
        "mma.sync.aligned.m16n8k16.row.col.f32.f16.f16.f32 "
        "{%0, %1, %2, %3}, {%4, %5, %6, %7}, {%8, %9}, {%0, %1, %2, %3};"
        : "+f"(d[0]), "+f"(d[1]), "+f"(d[2]), "+f"(d[3])
        : "r"(a[0]), "r"(a[1]), "r"(a[2]), "r"(a[3]), "r"(b0), "r"(b1));
}

// ============================================================================
// Kernel 0 (merged): x -> fp16 A-fragments, 2 m-tiles per block (ILP=2);
// blocks 0..15 also convert W1 -> paired fp16 B-fragments.
// grid = PREP_CTAS, block = 256 (kb x lane).
// ============================================================================
__global__ void prep_kernel(const float* __restrict__ x,
                            const float* __restrict__ W1,
                            int nN)
{
    const int bt   = blockIdx.x;
    const int kb   = threadIdx.x >> 5;
    const int lane = threadIdx.x & 31;
    const int r    = lane >> 2;
    const int k    = kb * 16 + (lane & 3) * 2;

    // ---- W part (first 16 blocks only) ----
    if (bt < 16) {
        const int n0 = bt * 16 + (lane >> 2);
        const int n1 = n0 + 8;
        const int k0 = kb * 16 + (lane & 3) * 2;
        const float* r0 = (n0 < 128) ? (W1 + (size_t)n0 * NCOLS)
                                     : (W1 + (size_t)(n0 - 128) * NCOLS + 128);
        const float* r1 = (n1 < 128) ? (W1 + (size_t)n1 * NCOLS)
                                     : (W1 + (size_t)(n1 - 128) * NCOLS + 128);
        g_W4[(bt * 8 + kb) * 32 + lane] =
            make_uint4(f2h2(r0[k0], r0[k0 + 1]), f2h2(r0[k0 + 8], r0[k0 + 9]),
                       f2h2(r1[k0], r1[k0 + 1]), f2h2(r1[k0 + 8], r1[k0 + 9]));
    }

    // ---- X part: two m-tiles, 8 independent loads in flight ----
    const float2 z = make_float2(0.f, 0.f);
    float2 v[2][4];
    #pragma unroll
    for (int u = 0; u < 2; u++) {
        const int mt = bt * 2 + u;
        const int m  = mt * 16 + r;
        const float* p0 = x + (size_t)m * D + k;
        const float* p1 = x + (size_t)(m + 8) * D + k;
        v[u][0] = (m < nN)     ? *reinterpret_cast<const float2*>(p0)     : z;
        v[u][1] = (m + 8 < nN) ? *reinterpret_cast<const float2*>(p1)     : z;
        v[u][2] = (m < nN)     ? *reinterpret_cast<const float2*>(p0 + 8) : z;
        v[u][3] = (m + 8 < nN) ? *reinterpret_cast<const float2*>(p1 + 8) : z;
    }
    #pragma unroll
    for (int u = 0; u < 2; u++) {
        const int mt = bt * 2 + u;
        if (mt < MAX_MT)
            g_X4[((size_t)mt * 8 + kb) * 32 + lane] =
                make_uint4(f2h2(v[u][0].x, v[u][0].y), f2h2(v[u][1].x, v[u][1].y),
                           f2h2(v[u][2].x, v[u][2].y), f2h2(v[u][3].x, v[u][3].y));
    }
}

// ============================================================================
// Kernel 1: P = x @ Bmat^T (fp16 m16n8k16, fp32 accum), pure fragment loads
// + A-fragment prefetch across kb. grid = N_CTAS (64 rows), block = 256
// (2 M x 4 N warps, warp tile 32x64). b1 folded into cols < 128. P fp16.
// ============================================================================
__global__ __launch_bounds__(256, 2) void precompute_kernel(
    const float* __restrict__ b1, int nN)
{
    const int tid  = threadIdx.x;
    const int wid  = tid >> 5;
    const int lane = tid & 31;
    const int wmg  = wid & 1;
    const int wng  = wid >> 1;
    const int wm   = wmg * 32;
    const int wjt  = wng * 8;
    const int r    = lane >> 2;
    const int c2   = (lane & 3) * 2;
    const int m0   = blockIdx.x * 64;
    const int mtb  = blockIdx.x * 4 + wmg * 2;

    float acc[2][8][4];
    #pragma unroll
    for (int i = 0; i < 2; i++)
        #pragma unroll
        for (int j = 0; j < 8; j++)
            #pragma unroll
            for (int q = 0; q < 4; q++) acc[i][j][q] = 0.f;

    // prologue: A fragments for kb=0
    uint4 A0 = g_X4[((size_t)mtb * 8 + 0) * 32 + lane];
    uint4 A1 = g_X4[((size_t)(mtb + 1) * 8 + 0) * 32 + lane];

    #pragma unroll
    for (int kb = 0; kb < 8; kb++) {
        u32 a[2][4];
        a[0][0] = A0.x; a[0][1] = A0.y; a[0][2] = A0.z; a[0][3] = A0.w;
        a[1][0] = A1.x; a[1][1] = A1.y; a[1][2] = A1.z; a[1][3] = A1.w;

        // prefetch next kb's A fragments (overlaps with the 16 HMMAs below)
        if (kb < 7) {
            A0 = g_X4[((size_t)mtb * 8 + kb + 1) * 32 + lane];
            A1 = g_X4[((size_t)(mtb + 1) * 8 + kb + 1) * 32 + lane];
        }

        #pragma unroll
        for (int jp = 0; jp < 4; jp++) {
            uint4 B = g_W4[(((wjt >> 1) + jp) * 8 + kb) * 32 + lane];
            mma_f16(acc[0][2 * jp],     a[0], B.x, B.y);
            mma_f16(acc[1][2 * jp],     a[1], B.x, B.y);
            mma_f16(acc[0][2 * jp + 1], a[0], B.z, B.w);
            mma_f16(acc[1][2 * jp + 1], a[1], B.z, B.w);
        }
    }

    #pragma unroll
    for (int j = 0; j < 8; j++) {
        const int col = (wjt + j) * 8 + c2;
        float2 bias = make_float2(0.f, 0.f);
        if (col < 128)
            bias = *reinterpret_cast<const float2*>(b1 + col);
        #pragma unroll
        for (int i = 0; i < 2; i++) {
            const int mA = m0 + wm + i * 16 + r;
            if (mA < nN) {
                *reinterpret_cast<u32*>(&g_Ph[(size_t)mA * NCOLS + col]) =
                    f2h2(acc[i][j][0] + bias.x, acc[i][j][1] + bias.y);
            }
            const int mB = mA + 8;
            if (mB < nN) {
                *reinterpret_cast<u32*>(&g_Ph[(size_t)mB * NCOLS + col]) =
                    f2h2(acc[i][j][2] + bias.x, acc[i][j][3] + bias.y);
            }
        }
    }
}

// ============================================================================
// Kernel 2: per-edge MLP tail (R16 verbatim). 8 lanes/edge, 4 slots/warp,
// ILP=3 + software-pipelined index prefetch.
//   v = sum_j max(PA[src][j] + PB[dst][j], 0) * w2[j]    (b1 already in PA)
//   out[e] = sigmoid(relu(v + b2))
// ============================================================================
__device__ __forceinline__ float dot16(uint4 ua, uint4 uc, const float* w) {
    const __half2 z2 = __float2half2_rn(0.f);
    const __half2* a2 = reinterpret_cast<const __half2*>(&ua);
    const __half2* c2 = reinterpret_cast<const __half2*>(&uc);
    float v = 0.f;
    #pragma unroll
    for (int i = 0; i < 4; i++) {
        __half2 h = __hmax2(__hadd2(a2[i], c2[i]), z2);
        float2 f = __half22float2(h);
        v = fmaf(f.x, w[2 * i], v);
        v = fmaf(f.y, w[2 * i + 1], v);
    }
    return v;
}

__global__ __launch_bounds__(256, 3) void edge_kernel(
    const void* __restrict__ edge_index,
    const float* __restrict__ W2,
    const float* __restrict__ b2,
    float* __restrict__ out,
    int E)
{
    const int lane   = threadIdx.x & 31;
    const int slot   = lane >> 3;
    const int sub    = lane & 7;
    const int warp   = (blockIdx.x * blockDim.x + threadIdx.x) >> 5;
    const int nwarps = (gridDim.x * blockDim.x) >> 5;
    const int step   = nwarps * 12;

    // dtype sniff: LE int64 (<2^31) => all odd 32-bit words zero
    const int* ei32 = (const int*)edge_index;
    int det = 0;
    #pragma unroll
    for (int i = 1; i < 16; i += 2) det |= __ldg(&ei32[i]);
    const bool is64 = (det == 0);
    const long long* ei64 = (const long long*)edge_index;

    float w0[8], w1[8];
    {
        const float4* w4 = reinterpret_cast<const float4*>(W2);
        float4 p0 = w4[sub * 2], p1 = w4[sub * 2 + 1];
        float4 p2 = w4[16 + sub * 2], p3 = w4[16 + sub * 2 + 1];
        w0[0]=p0.x; w0[1]=p0.y; w0[2]=p0.z; w0[3]=p0.w;
        w0[4]=p1.x; w0[5]=p1.y; w0[6]=p1.z; w0[7]=p1.w;
        w1[0]=p2.x; w1[1]=p2.y; w1[2]=p2.z; w1[3]=p2.w;
        w1[4]=p3.x; w1[5]=p3.y; w1[6]=p3.z; w1[7]=p3.w;
    }
    const float b2v = *b2;
    const __half* Ph = g_Ph;

    const int eb0 = warp * 12;
    if (eb0 >= E) return;

    int s[3], t[3];
    #pragma unroll
    for (int q = 0; q < 3; q++) {
        int er = eb0 + q * 4 + slot;
        int e  = (er < E) ? er : (E - 1);
        if (is64) { s[q] = (int)ei64[e]; t[q] = (int)ei64[E + e]; }
        else      { s[q] = ei32[e];      t[q] = ei32[E + e]; }
    }

    for (int eb = eb0; eb < E; eb += step) {
        uint4 a0[3], a1[3], c0[3], c1[3];
        #pragma unroll
        for (int q = 0; q < 3; q++) {
            const __half* rA = Ph + (size_t)s[q] * NCOLS;
            const __half* rC = Ph + (size_t)t[q] * NCOLS + 128;
            a0[q] = *reinterpret_cast<const uint4*>(rA + sub * 8);
            a1[q] = *reinterpret_cast<const uint4*>(rA + 64 + sub * 8);
            c0[q] = *reinterpret_cast<const uint4*>(rC + sub * 8);
            c1[q] = *reinterpret_cast<const uint4*>(rC + 64 + sub * 8);
        }

        const int nb = eb + step;
        if (nb < E) {
            #pragma unroll
            for (int q = 0; q < 3; q++) {
                int er = nb + q * 4 + slot;
                int e  = (er < E) ? er : (E - 1);
                if (is64) { s[q] = (int)ei64[e]; t[q] = (int)ei64[E + e]; }
                else      { s[q] = ei32[e];      t[q] = ei32[E + e]; }
            }
        }

        float v[3];
        #pragma unroll
        for (int q = 0; q < 3; q++)
            v[q] = dot16(a0[q], c0[q], w0) + dot16(a1[q], c1[q], w1);

        #pragma unroll
        for (int o = 4; o > 0; o >>= 1) {
            #pragma unroll
            for (int q = 0; q < 3; q++)
                v[q] += __shfl_xor_sync(0xFFFFFFFFu, v[q], o);
        }

        if (sub == 0) {
            #pragma unroll
            for (int q = 0; q < 3; q++) {
                int er = eb + q * 4 + slot;
                if (er < E) {
                    float h = fmaxf(v[q] + b2v, 0.f);
                    out[er] = 1.0f / (1.0f + __expf(-h));
                }
            }
        }
    }
}

// ============================================================================
// Launch
// Inputs: x[f32 N*128], edge_index[2*E i32/i64], W1[f32 128*256], b1[f32 128],
//         W2[f32 128], b2[f32 1]. Output: f32 E.
// ============================================================================
extern "C" void kernel_launch(void* const* d_in, const int* in_sizes, int n_in,
                              void* d_out, int out_size)
{
    const float* x  = (const float*)d_in[0];
    const void*  ei = d_in[1];
    const float* W1 = (const float*)d_in[2];
    const float* b1 = (const float*)d_in[3];
    const float* W2 = (const float*)d_in[4];
    const float* b2 = (const float*)d_in[5];
    float*       out = (float*)d_out;

    const int N = in_sizes[0] / D;   // 100000
    const int E = in_sizes[1] / 2;   // 625000

    prep_kernel<<<PREP_CTAS, 256>>>(x, W1, N);
    precompute_kernel<<<N_CTAS, 256>>>(b1, N);
    edge_kernel<<<1184, 256>>>(ei, W2, b2, out, E);
}